// round 4
// baseline (speedup 1.0000x reference)
#include <cuda_runtime.h>
#include <math.h>

#define N_EMB 8192
#define D_EMB 512
#define TILE  128
#define BK    16
#define NTILES (N_EMB / TILE)   // 64
#define NPAIR_TILES (NTILES * (NTILES + 1) / 2)  // 2080

// Scratch (allocation-free: __device__ globals)
__device__ float  g_norm[N_EMB * D_EMB];   // normalized embeddings, 16 MB
__device__ int    g_labels[N_EMB];
__device__ double g_acc;

// ---------------------------------------------------------------------------
// Kernel 0: detect label dtype (int32 vs little-endian int64), convert to
// int32 scratch, zero the accumulator. One block, 256 threads.
// If the buffer is int64, every odd int32 word is a high word == 0 (labels
// are 0..99). If int32, odd words are random labels in 0..99, so the chance
// all 256 are zero is ~1e-512.
// ---------------------------------------------------------------------------
__global__ void prep_labels_kernel(const int* __restrict__ raw) {
    __shared__ int s_or[256];
    int t = threadIdx.x;
    s_or[t] = raw[2 * t + 1];   // words 1,3,...,511 — in-bounds for both layouts
    __syncthreads();
    for (int s = 128; s > 0; s >>= 1) {
        if (t < s) s_or[t] |= s_or[t + s];
        __syncthreads();
    }
    int is64 = (s_or[0] == 0);
    for (int i = t; i < N_EMB; i += 256) {
        g_labels[i] = is64 ? raw[2 * i] : raw[i];
    }
    if (t == 0) g_acc = 0.0;
}

// ---------------------------------------------------------------------------
// Kernel 1: row-wise L2 normalize. One block (128 threads) per row; each
// thread owns one float4 of the 512-float row.
// ---------------------------------------------------------------------------
__global__ void normalize_kernel(const float* __restrict__ emb) {
    int row = blockIdx.x;
    const float4* src = reinterpret_cast<const float4*>(emb + (size_t)row * D_EMB);
    float4 v = src[threadIdx.x];
    float ss = v.x * v.x + v.y * v.y + v.z * v.z + v.w * v.w;
    #pragma unroll
    for (int o = 16; o > 0; o >>= 1) ss += __shfl_xor_sync(0xffffffffu, ss, o);
    __shared__ float ws[4];
    int lane = threadIdx.x & 31, w = threadIdx.x >> 5;
    if (lane == 0) ws[w] = ss;
    __syncthreads();
    float tot = ws[0] + ws[1] + ws[2] + ws[3];
    float inv = 1.0f / fmaxf(sqrtf(tot), 1e-12f);
    float4 o4 = make_float4(v.x * inv, v.y * inv, v.z * inv, v.w * inv);
    reinterpret_cast<float4*>(g_norm + (size_t)row * D_EMB)[threadIdx.x] = o4;
}

// ---------------------------------------------------------------------------
// Kernel 2: tiled pairwise loss. Only upper-triangular tiles (ti <= tj);
// off-diagonal tiles weighted x2. 128x128 tile, 256 threads, 8x8 per thread,
// BK=16 k-step. Smem tiles stored k-major (transposed) so both operand
// fragments read as conflict-free LDS.128.
// ---------------------------------------------------------------------------
__global__ __launch_bounds__(256, 2)
void pair_loss_kernel() {
    // Decode linear block id -> (ti, tj) with ti <= tj.
    // offset(ti) = ti*NTILES - ti*(ti-1)/2
    int b = blockIdx.x;
    float Tf = (float)NTILES;
    int ti = (int)floorf(((2.0f * Tf + 1.0f) -
              sqrtf((2.0f * Tf + 1.0f) * (2.0f * Tf + 1.0f) - 8.0f * (float)b)) * 0.5f);
    if (ti < 0) ti = 0;
    if (ti > NTILES - 1) ti = NTILES - 1;
    while ((ti + 1) * NTILES - ((ti + 1) * ti) / 2 <= b) ti++;
    while (ti * NTILES - (ti * (ti - 1)) / 2 > b) ti--;
    int tj = ti + (b - (ti * NTILES - (ti * (ti - 1)) / 2));

    int iBase = ti * TILE;
    int jBase = tj * TILE;

    __shared__ float As[BK][TILE];
    __shared__ float Bs[BK][TILE];
    __shared__ int   lA[TILE];
    __shared__ int   lB[TILE];

    int t  = threadIdx.x;
    int tx = t & 15;      // 0..15 -> n dimension
    int ty = t >> 4;      // 0..15 -> m dimension

    if (t < TILE)            lA[t]        = g_labels[iBase + t];
    else                     lB[t - TILE] = g_labels[jBase + (t - TILE)];

    const float* __restrict__ Abase = g_norm + (size_t)iBase * D_EMB;
    const float* __restrict__ Bbase = g_norm + (size_t)jBase * D_EMB;

    float acc[8][8];
    #pragma unroll
    for (int r = 0; r < 8; r++)
        #pragma unroll
        for (int c = 0; c < 8; c++) acc[r][c] = 0.0f;

    for (int k0 = 0; k0 < D_EMB; k0 += BK) {
        __syncthreads();   // protect smem reuse (also orders label loads on iter 0)
        // Load 128 rows x 16 k of A and B: 512 float4 each, 2 per thread.
        #pragma unroll
        for (int rep = 0; rep < 2; rep++) {
            int f   = t + rep * 256;      // 0..511
            int row = f >> 2;             // 0..127
            int kq  = f & 3;              // which float4 within the 16-k chunk
            const float4 av = *reinterpret_cast<const float4*>(
                Abase + (size_t)row * D_EMB + k0 + kq * 4);
            const float4 bv = *reinterpret_cast<const float4*>(
                Bbase + (size_t)row * D_EMB + k0 + kq * 4);
            int kk = kq * 4;
            As[kk + 0][row] = av.x; As[kk + 1][row] = av.y;
            As[kk + 2][row] = av.z; As[kk + 3][row] = av.w;
            Bs[kk + 0][row] = bv.x; Bs[kk + 1][row] = bv.y;
            Bs[kk + 2][row] = bv.z; Bs[kk + 3][row] = bv.w;
        }
        __syncthreads();

        #pragma unroll
        for (int k = 0; k < BK; k++) {
            float ar[8], br[8];
            *reinterpret_cast<float4*>(ar)     = *reinterpret_cast<const float4*>(&As[k][ty * 8]);
            *reinterpret_cast<float4*>(ar + 4) = *reinterpret_cast<const float4*>(&As[k][ty * 8 + 4]);
            *reinterpret_cast<float4*>(br)     = *reinterpret_cast<const float4*>(&Bs[k][tx * 8]);
            *reinterpret_cast<float4*>(br + 4) = *reinterpret_cast<const float4*>(&Bs[k][tx * 8 + 4]);
            #pragma unroll
            for (int r = 0; r < 8; r++)
                #pragma unroll
                for (int c = 0; c < 8; c++)
                    acc[r][c] = fmaf(ar[r], br[c], acc[r][c]);
        }
    }

    // Epilogue: loss per element, thread-local sum.
    float w = (ti == tj) ? 1.0f : 2.0f;
    float lsum = 0.0f;
    #pragma unroll
    for (int r = 0; r < 8; r++) {
        int mi = ty * 8 + r;
        int gi = iBase + mi;
        int li = lA[mi];
        #pragma unroll
        for (int c = 0; c < 8; c++) {
            int nj = tx * 8 + c;
            int gj = jBase + nj;
            float s = acc[r][c];
            float loss;
            if (li == lB[nj]) {
                float d = 1.0f - s;
                loss = d * d;
            } else {
                float d = fmaxf(s - 0.5f, 0.0f);
                loss = d * d;
            }
            if (gi == gj) loss = 0.0f;
            lsum += loss;
        }
    }
    lsum *= w;

    // Block reduction -> one double atomic per block.
    #pragma unroll
    for (int o = 16; o > 0; o >>= 1) lsum += __shfl_xor_sync(0xffffffffu, lsum, o);
    __shared__ float red[8];
    int lane = t & 31, warp = t >> 5;
    if (lane == 0) red[warp] = lsum;
    __syncthreads();
    if (t == 0) {
        float bs = 0.0f;
        #pragma unroll
        for (int i = 0; i < 8; i++) bs += red[i];
        atomicAdd(&g_acc, (double)bs);
    }
}

// ---------------------------------------------------------------------------
// Kernel 3: finalize scalar.
// ---------------------------------------------------------------------------
__global__ void finalize_kernel(float* __restrict__ out) {
    double denom = (double)N_EMB * (double)(N_EMB - 1);
    out[0] = (float)(g_acc / denom);
}

extern "C" void kernel_launch(void* const* d_in, const int* in_sizes, int n_in,
                              void* d_out, int out_size) {
    // Robust input-order resolution: embeddings has 8192*512 elements,
    // labels has 8192.
    const float* emb;
    const int*   lab;
    if (in_sizes[0] > in_sizes[1]) {
        emb = (const float*)d_in[0];
        lab = (const int*)d_in[1];
    } else {
        emb = (const float*)d_in[1];
        lab = (const int*)d_in[0];
    }
    float* out = (float*)d_out;

    prep_labels_kernel<<<1, 256>>>(lab);
    normalize_kernel<<<N_EMB, 128>>>(emb);
    pair_loss_kernel<<<NPAIR_TILES, 256>>>();
    finalize_kernel<<<1, 1>>>(out);
}

// round 8
// speedup vs baseline: 7.0459x; 7.0459x over previous
#include <cuda_runtime.h>
#include <cuda_bf16.h>
#include <math.h>
#include <stdint.h>

#define N_EMB 8192
#define D_EMB 512
#define TILE  128
#define KCHUNK 64
#define NCHUNKS (D_EMB / KCHUNK)                 // 8
#define NTILES (N_EMB / TILE)                    // 64
#define NPAIR_TILES (NTILES * (NTILES + 1) / 2)  // 2080
#define TMEM_COLS 128
#define SMEM_DYN (2 * 2 * TILE * KCHUNK * 2 + 1024)  // 66560 B

// Scratch (allocation-free: __device__ globals)
__device__ float         g_norm[N_EMB * D_EMB];    // fp32 normalized (SIMT fallback), 16 MB
__device__ __nv_bfloat16 g_normbf[N_EMB * D_EMB];  // bf16 normalized (tcgen05 path), 8 MB
__device__ int    g_labels[N_EMB];
__device__ double g_acc;

// ---------------------------------------------------------------------------
// PTX helpers
// ---------------------------------------------------------------------------
__device__ __forceinline__ uint32_t smem_u32(const void* p) {
    uint32_t a;
    asm("{ .reg .u64 t; cvta.to.shared.u64 t, %1; cvt.u32.u64 %0, t; }" : "=r"(a) : "l"(p));
    return a;
}
__device__ __forceinline__ uint32_t elect_one() {
    uint32_t r;
    asm volatile("{\n\t.reg .pred p;\n\telect.sync _|p, 0xFFFFFFFF;\n\tselp.b32 %0, 1, 0, p;\n\t}" : "=r"(r));
    return r;
}
#define MBARRIER_INIT(addr, cnt) \
    asm volatile("mbarrier.init.shared.b64 [%0], %1;" :: "r"(addr), "r"(cnt) : "memory")
#define MBARRIER_WAIT_P0(addr) do { \
    uint32_t _m = (addr); uint32_t _done; \
    asm volatile("{\n\t.reg .pred p;\n\tmbarrier.try_wait.parity.acquire.cta.shared::cta.b64 p, [%1], 0;\n\tselp.b32 %0,1,0,p;\n\t}" \
        : "=r"(_done) : "r"(_m) : "memory"); \
    if (!_done) { \
        asm volatile("{\n\t.reg .pred P1;\n\tWL_%=:\n\tmbarrier.try_wait.parity.acquire.cta.shared::cta.b64 P1, [%0], 0, 0x989680;\n\t@P1 bra.uni WD_%=;\n\tbra.uni WL_%=;\n\tWD_%=:\n\t}" \
            :: "r"(_m) : "memory"); \
    } } while (0)
#define FENCE_PROXY_ASYNC()    asm volatile("fence.proxy.async.shared::cta;" ::: "memory")
#define STS128(addr, a, b, c, d) \
    asm volatile("st.shared.v4.b32 [%0], {%1,%2,%3,%4};" :: "r"(addr), "r"(a), "r"(b), "r"(c), "r"(d) : "memory")

__device__ __forceinline__ uint32_t sw128(uint32_t off) { return off ^ ((off >> 3) & 0x70); }

#ifdef __CUDA_ARCH_FEAT_SM103_ALL
// ---- tcgen05 wrappers: ONLY compiled in the sm_103a feature pass ----------
#define TCGEN05_ALLOC(sa, n) \
    asm volatile("tcgen05.alloc.cta_group::1.sync.aligned.shared::cta.b32 [%0], %1;" :: "r"(sa), "r"(n) : "memory")
#define TCGEN05_DEALLOC(tm, n) \
    asm volatile("tcgen05.dealloc.cta_group::1.sync.aligned.b32 %0, %1;" :: "r"(tm), "r"(n))
#define TCGEN05_RELINQ() \
    asm volatile("tcgen05.relinquish_alloc_permit.cta_group::1.sync.aligned;")
#define TCGEN05_COMMIT(mb) \
    asm volatile("tcgen05.commit.cta_group::1.mbarrier::arrive::one.shared::cluster.b64 [%0];" :: "r"(mb) : "memory")
#define TCGEN05_FENCE_AFTER()  asm volatile("tcgen05.fence::after_thread_sync;" ::: "memory")
#define TCGEN05_FENCE_BEFORE() asm volatile("tcgen05.fence::before_thread_sync;" ::: "memory")
#define TCGEN05_WAIT_LD()      asm volatile("tcgen05.wait::ld.sync.aligned;" ::: "memory")
#define TCGEN05_LD_X32(r, ta) \
    asm volatile("tcgen05.ld.sync.aligned.32x32b.x32.b32 " \
        "{%0,%1,%2,%3,%4,%5,%6,%7,%8,%9,%10,%11,%12,%13,%14,%15," \
        "%16,%17,%18,%19,%20,%21,%22,%23,%24,%25,%26,%27,%28,%29,%30,%31}, [%32];" \
        : "=r"((r)[0]),"=r"((r)[1]),"=r"((r)[2]),"=r"((r)[3]),"=r"((r)[4]),"=r"((r)[5]),"=r"((r)[6]),"=r"((r)[7]), \
          "=r"((r)[8]),"=r"((r)[9]),"=r"((r)[10]),"=r"((r)[11]),"=r"((r)[12]),"=r"((r)[13]),"=r"((r)[14]),"=r"((r)[15]), \
          "=r"((r)[16]),"=r"((r)[17]),"=r"((r)[18]),"=r"((r)[19]),"=r"((r)[20]),"=r"((r)[21]),"=r"((r)[22]),"=r"((r)[23]), \
          "=r"((r)[24]),"=r"((r)[25]),"=r"((r)[26]),"=r"((r)[27]),"=r"((r)[28]),"=r"((r)[29]),"=r"((r)[30]),"=r"((r)[31]) \
        : "r"(ta))

// SS-mode bf16 MMA, cg1: D[M=128,N=128] += A[128,K16] * B[128,K16]^T
__device__ __forceinline__ void mma_f16_ss(uint32_t d_tmem, uint64_t a_desc, uint64_t b_desc,
                                           uint32_t idesc, uint32_t enable_d) {
    asm volatile(
        "{\n\t.reg .pred p;\n\tsetp.ne.u32 p, %4, 0;\n\t"
        "tcgen05.mma.cta_group::1.kind::f16 [%0], %1, %2, %3, {%5,%5,%5,%5}, p;\n\t}"
        :: "r"(d_tmem), "l"(a_desc), "l"(b_desc), "r"(idesc), "r"(enable_d), "r"(0u)
        : "memory");
}
#endif  // __CUDA_ARCH_FEAT_SM103_ALL

// SW128 K-major smem descriptor base (layout=SW128, version=1, SBO=64, LBO=1)
__device__ static const uint64_t DESC_BASE =
    (2ull << 61) | (1ull << 46) | (64ull << 32) | (1ull << 16);
// idesc: F32 accum, bf16 x bf16, N=128, M=128
#define MMA_IDESC 0x8200490u

// ---------------------------------------------------------------------------
// Kernel 0: detect label dtype (int32 vs LE int64), convert, zero accumulator.
// labels < 100 => for an int64 buffer every odd 32-bit word is 0.
// ---------------------------------------------------------------------------
__global__ void prep_labels_kernel(const int* __restrict__ raw) {
    __shared__ int s_or[256];
    int t = threadIdx.x;
    s_or[t] = raw[2 * t + 1];
    __syncthreads();
    for (int s = 128; s > 0; s >>= 1) {
        if (t < s) s_or[t] |= s_or[t + s];
        __syncthreads();
    }
    int is64 = (s_or[0] == 0);
    for (int i = t; i < N_EMB; i += 256) g_labels[i] = is64 ? raw[2 * i] : raw[i];
    if (t == 0) g_acc = 0.0;
}

// ---------------------------------------------------------------------------
// Kernel 1: row-wise L2 normalize; emit fp32 AND bf16. 128 threads / row.
// ---------------------------------------------------------------------------
__global__ void normalize_kernel(const float* __restrict__ emb) {
    int row = blockIdx.x;
    const float4* src = reinterpret_cast<const float4*>(emb + (size_t)row * D_EMB);
    float4 v = src[threadIdx.x];
    float ss = v.x * v.x + v.y * v.y + v.z * v.z + v.w * v.w;
    #pragma unroll
    for (int o = 16; o > 0; o >>= 1) ss += __shfl_xor_sync(0xffffffffu, ss, o);
    __shared__ float ws[4];
    int lane = threadIdx.x & 31, w = threadIdx.x >> 5;
    if (lane == 0) ws[w] = ss;
    __syncthreads();
    float tot = ws[0] + ws[1] + ws[2] + ws[3];
    float inv = 1.0f / fmaxf(sqrtf(tot), 1e-12f);
    float4 f = make_float4(v.x * inv, v.y * inv, v.z * inv, v.w * inv);
    reinterpret_cast<float4*>(g_norm + (size_t)row * D_EMB)[threadIdx.x] = f;
    __nv_bfloat162 p0 = __float22bfloat162_rn(make_float2(f.x, f.y));
    __nv_bfloat162 p1 = __float22bfloat162_rn(make_float2(f.z, f.w));
    uint2 o2;
    o2.x = *reinterpret_cast<uint32_t*>(&p0);
    o2.y = *reinterpret_cast<uint32_t*>(&p1);
    reinterpret_cast<uint2*>(g_normbf + (size_t)row * D_EMB)[threadIdx.x] = o2;
}

// ---------------------------------------------------------------------------
// Kernel 2: pairwise Gram-tile + loss. 128x128 tile per CTA, upper-triangular
// tiles only (off-diag weighted x2).
//   sm_103a pass : tcgen05 bf16 SS MMA, double-buffered SMEM, TMEM epilogue.
//   other passes : fp32 SIMT register-blocked GEMM (proven 825us fallback).
// ---------------------------------------------------------------------------
extern __shared__ char dynsmem[];

__global__ __launch_bounds__(256, 2)
void pair_loss_kernel() {
    // Decode linear block id -> (ti, tj), ti <= tj.
    int b = blockIdx.x;
    float Tf = (float)NTILES;
    int ti = (int)floorf(((2.0f * Tf + 1.0f) -
              sqrtf((2.0f * Tf + 1.0f) * (2.0f * Tf + 1.0f) - 8.0f * (float)b)) * 0.5f);
    if (ti < 0) ti = 0;
    if (ti > NTILES - 1) ti = NTILES - 1;
    while ((ti + 1) * NTILES - ((ti + 1) * ti) / 2 <= b) ti++;
    while (ti * NTILES - (ti * (ti - 1)) / 2 > b) ti--;
    int tj = ti + (b - (ti * NTILES - (ti * (ti - 1)) / 2));
    int iBase = ti * TILE;
    int jBase = tj * TILE;

    int t = threadIdx.x, lane = t & 31, w = t >> 5;

#ifdef __CUDA_ARCH_FEAT_SM103_ALL
    // ============================ tcgen05 path =============================
    __shared__ uint32_t s_tmem;
    __shared__ alignas(8) unsigned long long s_mbar[NCHUNKS];
    __shared__ int sLA[TILE], sLB[TILE];
    __shared__ float s_red[8];

    uint32_t base = (smem_u32(dynsmem) + 1023u) & ~1023u;
    uint32_t mbar0 = smem_u32(s_mbar);

    if (t < TILE) sLA[t] = g_labels[iBase + t];
    else          sLB[t - TILE] = g_labels[jBase + (t - TILE)];
    if (t == 0) {
        #pragma unroll
        for (int i = 0; i < NCHUNKS; i++) MBARRIER_INIT(mbar0 + 8 * i, 1);
    }
    if (w == 0) TCGEN05_ALLOC(smem_u32(&s_tmem), TMEM_COLS);
    __syncthreads();
    uint32_t tmem;
    asm volatile("ld.shared.b32 %0, [%1];" : "=r"(tmem) : "r"(smem_u32(&s_tmem)));

    const __nv_bfloat16* __restrict__ Arow = g_normbf + (size_t)iBase * D_EMB;
    const __nv_bfloat16* __restrict__ Brow = g_normbf + (size_t)jBase * D_EMB;

    for (int kc = 0; kc < NCHUNKS; kc++) {
        if (kc >= 2) { MBARRIER_WAIT_P0(mbar0 + 8 * (kc - 2)); }
        uint32_t bufA = base + (uint32_t)(kc & 1) * 32768u;
        uint32_t bufB = bufA + 16384u;
        int k0 = kc * KCHUNK;

        // 128 rows x 64 k bf16 of A and B: 1024 uint4 each; 4 per thread each.
        #pragma unroll
        for (int p = 0; p < 4; p++) {
            int f = p * 256 + t;          // 0..1023
            int row = f >> 3;             // 0..127
            int kq  = f & 7;              // 16B group within the 128B row
            uint32_t soff = sw128((uint32_t)(row * 128 + kq * 16));
            const uint4 av = *reinterpret_cast<const uint4*>(Arow + (size_t)row * D_EMB + k0 + kq * 8);
            STS128(bufA + soff, av.x, av.y, av.z, av.w);
            const uint4 bv = *reinterpret_cast<const uint4*>(Brow + (size_t)row * D_EMB + k0 + kq * 8);
            STS128(bufB + soff, bv.x, bv.y, bv.z, bv.w);
        }
        FENCE_PROXY_ASYNC();
        __syncthreads();

        if (w == 0) {
            if (elect_one()) {
                uint64_t ad = DESC_BASE | ((uint64_t)(bufA >> 4) & 0x3FFFull);
                uint64_t bd = DESC_BASE | ((uint64_t)(bufB >> 4) & 0x3FFFull);
                #pragma unroll
                for (int s = 0; s < 4; s++) {   // 4 x K=16 bf16 sub-steps
                    mma_f16_ss(tmem, ad + (uint64_t)(s * 2), bd + (uint64_t)(s * 2),
                               MMA_IDESC, (kc > 0 || s > 0) ? 1u : 0u);
                }
                TCGEN05_COMMIT(mbar0 + 8 * kc);
            }
        }
    }

    MBARRIER_WAIT_P0(mbar0 + 8 * (NCHUNKS - 1));
    TCGEN05_FENCE_AFTER();

    // Epilogue: warp w (SMSP w&3) reads its TMEM subpartition rows,
    // columns 64*(w>>2)..+63. Two warps per subpartition cover 128 cols.
    int sp = w & 3;
    int m = sp * 32 + lane;
    int li = sLA[m];
    uint32_t woff = (uint32_t)sp << 21;
    float wgt = (ti == tj) ? 1.0f : 2.0f;
    bool diag = (ti == tj);

    float lsum = 0.0f;
    #pragma unroll
    for (int cb = 0; cb < 2; cb++) {
        int c0 = (w >> 2) * 64 + cb * 32;
        uint32_t regs[32];
        TCGEN05_LD_X32(regs, tmem + (uint32_t)c0 + woff);
        TCGEN05_WAIT_LD();
        #pragma unroll
        for (int c = 0; c < 32; c++) {
            int n = c0 + c;
            float s = __uint_as_float(regs[c]);
            float loss;
            if (li == sLB[n]) { float d = 1.0f - s;              loss = d * d; }
            else              { float d = fmaxf(s - 0.5f, 0.0f); loss = d * d; }
            if (diag && m == n) loss = 0.0f;
            lsum += loss;
        }
    }
    TCGEN05_FENCE_BEFORE();
    lsum *= wgt;

    #pragma unroll
    for (int o = 16; o > 0; o >>= 1) lsum += __shfl_xor_sync(0xffffffffu, lsum, o);
    if (lane == 0) s_red[w] = lsum;
    __syncthreads();
    if (t == 0) {
        float bs = 0.0f;
        #pragma unroll
        for (int i = 0; i < 8; i++) bs += s_red[i];
        atomicAdd(&g_acc, (double)bs);
    }

    __syncthreads();
    if (w == 0) {
        TCGEN05_RELINQ();
        TCGEN05_DEALLOC(tmem, TMEM_COLS);
    }
#else
    // ========================= fp32 SIMT fallback ==========================
    #define BK 16
    __shared__ float As[BK][TILE];
    __shared__ float Bs[BK][TILE];
    __shared__ int   lA[TILE];
    __shared__ int   lB[TILE];
    __shared__ float red[8];

    int tx = t & 15;
    int ty = t >> 4;

    if (t < TILE)            lA[t]        = g_labels[iBase + t];
    else                     lB[t - TILE] = g_labels[jBase + (t - TILE)];

    const float* __restrict__ Abase = g_norm + (size_t)iBase * D_EMB;
    const float* __restrict__ Bbase = g_norm + (size_t)jBase * D_EMB;

    float acc[8][8];
    #pragma unroll
    for (int r = 0; r < 8; r++)
        #pragma unroll
        for (int c = 0; c < 8; c++) acc[r][c] = 0.0f;

    for (int k0 = 0; k0 < D_EMB; k0 += BK) {
        __syncthreads();
        #pragma unroll
        for (int rep = 0; rep < 2; rep++) {
            int f   = t + rep * 256;
            int row = f >> 2;
            int kq  = f & 3;
            const float4 av = *reinterpret_cast<const float4*>(
                Abase + (size_t)row * D_EMB + k0 + kq * 4);
            const float4 bv = *reinterpret_cast<const float4*>(
                Bbase + (size_t)row * D_EMB + k0 + kq * 4);
            int kk = kq * 4;
            As[kk + 0][row] = av.x; As[kk + 1][row] = av.y;
            As[kk + 2][row] = av.z; As[kk + 3][row] = av.w;
            Bs[kk + 0][row] = bv.x; Bs[kk + 1][row] = bv.y;
            Bs[kk + 2][row] = bv.z; Bs[kk + 3][row] = bv.w;
        }
        __syncthreads();

        #pragma unroll
        for (int k = 0; k < BK; k++) {
            float ar[8], br[8];
            *reinterpret_cast<float4*>(ar)     = *reinterpret_cast<const float4*>(&As[k][ty * 8]);
            *reinterpret_cast<float4*>(ar + 4) = *reinterpret_cast<const float4*>(&As[k][ty * 8 + 4]);
            *reinterpret_cast<float4*>(br)     = *reinterpret_cast<const float4*>(&Bs[k][tx * 8]);
            *reinterpret_cast<float4*>(br + 4) = *reinterpret_cast<const float4*>(&Bs[k][tx * 8 + 4]);
            #pragma unroll
            for (int r = 0; r < 8; r++)
                #pragma unroll
                for (int c = 0; c < 8; c++)
                    acc[r][c] = fmaf(ar[r], br[c], acc[r][c]);
        }
    }

    float wgt = (ti == tj) ? 1.0f : 2.0f;
    float lsum = 0.0f;
    #pragma unroll
    for (int r = 0; r < 8; r++) {
        int mi = ty * 8 + r;
        int gi = iBase + mi;
        int li = lA[mi];
        #pragma unroll
        for (int c = 0; c < 8; c++) {
            int nj = tx * 8 + c;
            int gj = jBase + nj;
            float s = acc[r][c];
            float loss;
            if (li == lB[nj]) { float d = 1.0f - s;              loss = d * d; }
            else              { float d = fmaxf(s - 0.5f, 0.0f); loss = d * d; }
            if (gi == gj) loss = 0.0f;
            lsum += loss;
        }
    }
    lsum *= wgt;

    #pragma unroll
    for (int o = 16; o > 0; o >>= 1) lsum += __shfl_xor_sync(0xffffffffu, lsum, o);
    if (lane == 0) red[w] = lsum;
    __syncthreads();
    if (t == 0) {
        float bs = 0.0f;
        #pragma unroll
        for (int i = 0; i < 8; i++) bs += red[i];
        atomicAdd(&g_acc, (double)bs);
    }
    #undef BK
#endif
}

// ---------------------------------------------------------------------------
// Kernel 3: finalize scalar.
// ---------------------------------------------------------------------------
__global__ void finalize_kernel(float* __restrict__ out) {
    double denom = (double)N_EMB * (double)(N_EMB - 1);
    out[0] = (float)(g_acc / denom);
}

extern "C" void kernel_launch(void* const* d_in, const int* in_sizes, int n_in,
                              void* d_out, int out_size) {
    const float* emb;
    const int*   lab;
    if (in_sizes[0] > in_sizes[1]) {
        emb = (const float*)d_in[0];
        lab = (const int*)d_in[1];
    } else {
        emb = (const float*)d_in[1];
        lab = (const int*)d_in[0];
    }
    float* out = (float*)d_out;

    // Idempotent; not a stream op, safe under graph capture.
    (void)cudaFuncSetAttribute(pair_loss_kernel,
                               cudaFuncAttributeMaxDynamicSharedMemorySize, SMEM_DYN);

    prep_labels_kernel<<<1, 256>>>(lab);
    normalize_kernel<<<N_EMB, 128>>>(emb);
    pair_loss_kernel<<<NPAIR_TILES, 256, SMEM_DYN>>>();
    finalize_kernel<<<1, 1>>>(out);
}

// round 10
// speedup vs baseline: 10.0190x; 1.4220x over previous
#include <cuda_runtime.h>
#include <cuda_bf16.h>
#include <math.h>
#include <stdint.h>

#define N_EMB 8192
#define D_EMB 512
#define TILE_M 128
#define TILE_N 256
#define KCHUNK 64
#define NCHUNKS (D_EMB / KCHUNK)                  // 8
#define NT_M (N_EMB / TILE_M)                     // 64
#define NT_N (N_EMB / TILE_N)                     // 32
#define GRID_PAIR (NT_N * (NT_N + 1))             // sum(2cj+2) = 1056
#define TMEM_COLS 256
// per stage: A 16KB + B 32KB; 2 stages + 1KB align pad
#define A_STAGE 16384
#define B_STAGE 32768
#define STAGE_BYTES (A_STAGE + B_STAGE)
#define SMEM_DYN (2 * STAGE_BYTES + 1024)         // 99328

// Scratch (allocation-free: __device__ globals)
__device__ __nv_bfloat16 g_normbf[N_EMB * D_EMB];  // bf16 normalized, 8 MB
__device__ int    g_labels[N_EMB];
__device__ double g_acc;
__device__ int    g_done;

// ---------------------------------------------------------------------------
// PTX helpers
// ---------------------------------------------------------------------------
__device__ __forceinline__ uint32_t smem_u32(const void* p) {
    uint32_t a;
    asm("{ .reg .u64 t; cvta.to.shared.u64 t, %1; cvt.u32.u64 %0, t; }" : "=r"(a) : "l"(p));
    return a;
}
__device__ __forceinline__ uint32_t elect_one() {
    uint32_t r;
    asm volatile("{\n\t.reg .pred p;\n\telect.sync _|p, 0xFFFFFFFF;\n\tselp.b32 %0, 1, 0, p;\n\t}" : "=r"(r));
    return r;
}
#define MBARRIER_INIT(addr, cnt) \
    asm volatile("mbarrier.init.shared.b64 [%0], %1;" :: "r"(addr), "r"(cnt) : "memory")
#define MBARRIER_WAIT_P0(addr) do { \
    uint32_t _m = (addr); uint32_t _done; \
    asm volatile("{\n\t.reg .pred p;\n\tmbarrier.try_wait.parity.acquire.cta.shared::cta.b64 p, [%1], 0;\n\tselp.b32 %0,1,0,p;\n\t}" \
        : "=r"(_done) : "r"(_m) : "memory"); \
    if (!_done) { \
        asm volatile("{\n\t.reg .pred P1;\n\tWL_%=:\n\tmbarrier.try_wait.parity.acquire.cta.shared::cta.b64 P1, [%0], 0, 0x989680;\n\t@P1 bra.uni WD_%=;\n\tbra.uni WL_%=;\n\tWD_%=:\n\t}" \
            :: "r"(_m) : "memory"); \
    } } while (0)
#define FENCE_PROXY_ASYNC()    asm volatile("fence.proxy.async.shared::cta;" ::: "memory")
#define CP_ASYNC16(daddr, gptr) \
    asm volatile("cp.async.cg.shared.global [%0], [%1], 16;" :: "r"(daddr), "l"(gptr) : "memory")
#define CP_ASYNC_COMMIT() asm volatile("cp.async.commit_group;" ::: "memory")
#define CP_ASYNC_WAIT0()  asm volatile("cp.async.wait_group 0;" ::: "memory")

__device__ __forceinline__ uint32_t sw128(uint32_t off) { return off ^ ((off >> 3) & 0x70); }

#ifdef __CUDA_ARCH_FEAT_SM103_ALL
// ---- tcgen05 wrappers: ONLY compiled in the sm_103a feature pass ----------
#define TCGEN05_ALLOC(sa, n) \
    asm volatile("tcgen05.alloc.cta_group::1.sync.aligned.shared::cta.b32 [%0], %1;" :: "r"(sa), "r"(n) : "memory")
#define TCGEN05_DEALLOC(tm, n) \
    asm volatile("tcgen05.dealloc.cta_group::1.sync.aligned.b32 %0, %1;" :: "r"(tm), "r"(n))
#define TCGEN05_RELINQ() \
    asm volatile("tcgen05.relinquish_alloc_permit.cta_group::1.sync.aligned;")
#define TCGEN05_COMMIT(mb) \
    asm volatile("tcgen05.commit.cta_group::1.mbarrier::arrive::one.shared::cluster.b64 [%0];" :: "r"(mb) : "memory")
#define TCGEN05_FENCE_AFTER()  asm volatile("tcgen05.fence::after_thread_sync;" ::: "memory")
#define TCGEN05_FENCE_BEFORE() asm volatile("tcgen05.fence::before_thread_sync;" ::: "memory")
#define TCGEN05_WAIT_LD()      asm volatile("tcgen05.wait::ld.sync.aligned;" ::: "memory")
#define TCGEN05_LD_X32(r, ta) \
    asm volatile("tcgen05.ld.sync.aligned.32x32b.x32.b32 " \
        "{%0,%1,%2,%3,%4,%5,%6,%7,%8,%9,%10,%11,%12,%13,%14,%15," \
        "%16,%17,%18,%19,%20,%21,%22,%23,%24,%25,%26,%27,%28,%29,%30,%31}, [%32];" \
        : "=r"((r)[0]),"=r"((r)[1]),"=r"((r)[2]),"=r"((r)[3]),"=r"((r)[4]),"=r"((r)[5]),"=r"((r)[6]),"=r"((r)[7]), \
          "=r"((r)[8]),"=r"((r)[9]),"=r"((r)[10]),"=r"((r)[11]),"=r"((r)[12]),"=r"((r)[13]),"=r"((r)[14]),"=r"((r)[15]), \
          "=r"((r)[16]),"=r"((r)[17]),"=r"((r)[18]),"=r"((r)[19]),"=r"((r)[20]),"=r"((r)[21]),"=r"((r)[22]),"=r"((r)[23]), \
          "=r"((r)[24]),"=r"((r)[25]),"=r"((r)[26]),"=r"((r)[27]),"=r"((r)[28]),"=r"((r)[29]),"=r"((r)[30]),"=r"((r)[31]) \
        : "r"(ta))

// SS-mode bf16 MMA, cg1: D[M=128,N=256] += A[128,K16] * B[256,K16]^T
__device__ __forceinline__ void mma_f16_ss(uint32_t d_tmem, uint64_t a_desc, uint64_t b_desc,
                                           uint32_t idesc, uint32_t enable_d) {
    asm volatile(
        "{\n\t.reg .pred p;\n\tsetp.ne.u32 p, %4, 0;\n\t"
        "tcgen05.mma.cta_group::1.kind::f16 [%0], %1, %2, %3, {%5,%5,%5,%5}, p;\n\t}"
        :: "r"(d_tmem), "l"(a_desc), "l"(b_desc), "r"(idesc), "r"(enable_d), "r"(0u)
        : "memory");
}
#endif  // __CUDA_ARCH_FEAT_SM103_ALL

// SW128 K-major smem descriptor base (layout=SW128, version=1, SBO=64, LBO=1)
__device__ static const uint64_t DESC_BASE =
    (2ull << 61) | (1ull << 46) | (64ull << 32) | (1ull << 16);
// idesc: F32 accum (1<<4), bf16 A (1<<7), bf16 B (1<<10), N=256 (32<<17), M=128 (8<<24)
#define MMA_IDESC 0x8400490u

// ---------------------------------------------------------------------------
// Kernel 1: fused label-prep + row-wise L2 normalize (bf16 out).
// Grid = N_EMB + 1: block N_EMB does labels + accumulator init; others
// normalize one row each (128 threads, one float4 per thread).
// ---------------------------------------------------------------------------
__global__ void prep_normalize_kernel(const float* __restrict__ emb,
                                      const int* __restrict__ raw) {
    if (blockIdx.x == N_EMB) {
        // Label dtype detection: labels < 100, so an int64 buffer has all odd
        // 32-bit words zero; int32 has random labels there (P(all 0) ~1e-256).
        __shared__ int s_or[128];
        int t = threadIdx.x;
        s_or[t] = raw[2 * t + 1];
        __syncthreads();
        for (int s = 64; s > 0; s >>= 1) {
            if (t < s) s_or[t] |= s_or[t + s];
            __syncthreads();
        }
        int is64 = (s_or[0] == 0);
        for (int i = t; i < N_EMB; i += 128) g_labels[i] = is64 ? raw[2 * i] : raw[i];
        if (t == 0) { g_acc = 0.0; g_done = 0; }
        return;
    }
    int row = blockIdx.x;
    const float4* src = reinterpret_cast<const float4*>(emb + (size_t)row * D_EMB);
    float4 v = src[threadIdx.x];
    float ss = v.x * v.x + v.y * v.y + v.z * v.z + v.w * v.w;
    #pragma unroll
    for (int o = 16; o > 0; o >>= 1) ss += __shfl_xor_sync(0xffffffffu, ss, o);
    __shared__ float ws[4];
    int lane = threadIdx.x & 31, w = threadIdx.x >> 5;
    if (lane == 0) ws[w] = ss;
    __syncthreads();
    float tot = ws[0] + ws[1] + ws[2] + ws[3];
    float inv = 1.0f / fmaxf(sqrtf(tot), 1e-12f);
    __nv_bfloat162 p0 = __float22bfloat162_rn(make_float2(v.x * inv, v.y * inv));
    __nv_bfloat162 p1 = __float22bfloat162_rn(make_float2(v.z * inv, v.w * inv));
    uint2 o2;
    o2.x = *reinterpret_cast<uint32_t*>(&p0);
    o2.y = *reinterpret_cast<uint32_t*>(&p1);
    reinterpret_cast<uint2*>(g_normbf + (size_t)row * D_EMB)[threadIdx.x] = o2;
}

// ---------------------------------------------------------------------------
// Kernel 2: pairwise Gram-tile + loss + fused finalize.
// Tiles: M=128 rows (ti in 0..63) x N=256 cols (cj in 0..31), included iff
// the tile intersects the strict upper triangle (ti <= 2cj+1) => 1056 tiles.
// Per-element weight: gj>gi ? 2 : 0 (covers diagonal + sub-diagonal waste).
//   sm_103a pass : tcgen05 bf16 SS MMA, cp.async double-buffered SMEM, TMEM.
//   other passes : bf16->fp32 SIMT fallback (compile-safety only; not run).
// ---------------------------------------------------------------------------
extern __shared__ char dynsmem[];

__global__ __launch_bounds__(256, 2)
void pair_loss_kernel(float* __restrict__ out) {
    // Decode linear block id -> (cj, ti). offset(cj) = cj*(cj+1).
    int b = blockIdx.x;
    int cj = (int)((sqrtf(4.0f * (float)b + 1.0f) - 1.0f) * 0.5f);
    if (cj < 0) cj = 0;
    if (cj > NT_N - 1) cj = NT_N - 1;
    while (cj * (cj + 1) > b) cj--;
    while ((cj + 1) * (cj + 2) <= b) cj++;
    int ti = b - cj * (cj + 1);
    int iBase = ti * TILE_M;
    int jBase = cj * TILE_N;

    int t = threadIdx.x, lane = t & 31, w = t >> 5;

#ifdef __CUDA_ARCH_FEAT_SM103_ALL
    // ============================ tcgen05 path =============================
    __shared__ uint32_t s_tmem;
    __shared__ alignas(8) unsigned long long s_mbar[NCHUNKS];
    __shared__ int sLA[TILE_M], sLB[TILE_N];
    __shared__ float s_red[8];

    uint32_t base = (smem_u32(dynsmem) + 1023u) & ~1023u;
    uint32_t mbar0 = smem_u32(s_mbar);

    if (t < TILE_M) sLA[t] = g_labels[iBase + t];
    sLB[t] = g_labels[jBase + t];
    if (t == 0) {
        #pragma unroll
        for (int i = 0; i < NCHUNKS; i++) MBARRIER_INIT(mbar0 + 8 * i, 1);
    }
    if (w == 0) TCGEN05_ALLOC(smem_u32(&s_tmem), TMEM_COLS);
    __syncthreads();
    uint32_t tmem;
    asm volatile("ld.shared.b32 %0, [%1];" : "=r"(tmem) : "r"(smem_u32(&s_tmem)));

    const __nv_bfloat16* __restrict__ Arow = g_normbf + (size_t)iBase * D_EMB;
    const __nv_bfloat16* __restrict__ Brow = g_normbf + (size_t)jBase * D_EMB;

    // Per-thread constant addressing: thread covers rows f>>3, 16B-group f&7.
    for (int kc = 0; kc < NCHUNKS; kc++) {
        if (kc >= 2) { MBARRIER_WAIT_P0(mbar0 + 8 * (kc - 2)); }
        uint32_t bufA = base + (uint32_t)(kc & 1) * STAGE_BYTES;
        uint32_t bufB = bufA + A_STAGE;
        int k0 = kc * KCHUNK;

        // A: 128 rows x 128 B = 1024 x 16B -> 4 per thread.
        #pragma unroll
        for (int p = 0; p < 4; p++) {
            int f = p * 256 + t;
            int row = f >> 3, kq = f & 7;
            uint32_t soff = sw128((uint32_t)(row * 128 + kq * 16));
            CP_ASYNC16(bufA + soff, Arow + (size_t)row * D_EMB + k0 + kq * 8);
        }
        // B: 256 rows x 128 B = 2048 x 16B -> 8 per thread.
        #pragma unroll
        for (int p = 0; p < 8; p++) {
            int f = p * 256 + t;
            int row = f >> 3, kq = f & 7;
            uint32_t soff = sw128((uint32_t)(row * 128 + kq * 16));
            CP_ASYNC16(bufB + soff, Brow + (size_t)row * D_EMB + k0 + kq * 8);
        }
        CP_ASYNC_COMMIT();
        CP_ASYNC_WAIT0();
        FENCE_PROXY_ASYNC();
        __syncthreads();

        if (w == 0) {
            if (elect_one()) {
                uint64_t ad = DESC_BASE | ((uint64_t)(bufA >> 4) & 0x3FFFull);
                uint64_t bd = DESC_BASE | ((uint64_t)(bufB >> 4) & 0x3FFFull);
                #pragma unroll
                for (int s = 0; s < 4; s++) {   // 4 x K=16 bf16 sub-steps
                    mma_f16_ss(tmem, ad + (uint64_t)(s * 2), bd + (uint64_t)(s * 2),
                               MMA_IDESC, (kc > 0 || s > 0) ? 1u : 0u);
                }
                TCGEN05_COMMIT(mbar0 + 8 * kc);
            }
        }
    }

    MBARRIER_WAIT_P0(mbar0 + 8 * (NCHUNKS - 1));
    TCGEN05_FENCE_AFTER();

    // Epilogue: warp w (SMSP w&3) covers TMEM rows (w&3)*32+lane,
    // columns (w>>2)*128 .. +127 in four x32 loads.
    int sp = w & 3;
    int m = sp * 32 + lane;
    int gi = iBase + m;
    int li = sLA[m];
    uint32_t woff = (uint32_t)sp << 21;

    float lsum = 0.0f;
    #pragma unroll
    for (int cb = 0; cb < 4; cb++) {
        int c0 = (w >> 2) * 128 + cb * 32;
        uint32_t regs[32];
        TCGEN05_LD_X32(regs, tmem + (uint32_t)c0 + woff);
        TCGEN05_WAIT_LD();
        #pragma unroll
        for (int c = 0; c < 32; c++) {
            int n = c0 + c;
            int gj = jBase + n;
            float s = __uint_as_float(regs[c]);
            float loss;
            if (li == sLB[n]) { float d = 1.0f - s;              loss = d * d; }
            else              { float d = fmaxf(s - 0.5f, 0.0f); loss = d * d; }
            lsum += (gj > gi) ? 2.0f * loss : 0.0f;
        }
    }
    TCGEN05_FENCE_BEFORE();

    #pragma unroll
    for (int o = 16; o > 0; o >>= 1) lsum += __shfl_xor_sync(0xffffffffu, lsum, o);
    if (lane == 0) s_red[w] = lsum;
    __syncthreads();
    if (t == 0) {
        float bs = 0.0f;
        #pragma unroll
        for (int i = 0; i < 8; i++) bs += s_red[i];
        atomicAdd(&g_acc, (double)bs);
        __threadfence();
        int old = atomicAdd(&g_done, 1);
        if (old == GRID_PAIR - 1) {
            __threadfence();
            double total = atomicAdd(&g_acc, 0.0);
            out[0] = (float)(total / ((double)N_EMB * (double)(N_EMB - 1)));
        }
    }

    __syncthreads();
    if (w == 0) {
        TCGEN05_RELINQ();
        TCGEN05_DEALLOC(tmem, TMEM_COLS);
    }
#else
    // ===================== SIMT fallback (compile-only) ====================
    #define BK 16
    __shared__ float As[BK][TILE_M];
    __shared__ float Bs[BK][TILE_M];
    __shared__ int   lA[TILE_M];
    __shared__ int   lB[TILE_N];
    __shared__ float red[8];

    int tx = t & 15;
    int ty = t >> 4;

    if (t < TILE_M) lA[t] = g_labels[iBase + t];
    lB[t] = g_labels[jBase + t];

    float lsum = 0.0f;
    for (int half = 0; half < 2; half++) {
        int jb = jBase + half * TILE_M;
        const __nv_bfloat16* __restrict__ Abase = g_normbf + (size_t)iBase * D_EMB;
        const __nv_bfloat16* __restrict__ Bbase = g_normbf + (size_t)jb * D_EMB;

        float acc[8][8];
        #pragma unroll
        for (int r = 0; r < 8; r++)
            #pragma unroll
            for (int c = 0; c < 8; c++) acc[r][c] = 0.0f;

        for (int k0 = 0; k0 < D_EMB; k0 += BK) {
            __syncthreads();
            #pragma unroll
            for (int rep = 0; rep < 2; rep++) {
                int f   = t + rep * 256;
                int row = f >> 2;
                int kq  = f & 3;
                uint2 au = *reinterpret_cast<const uint2*>(Abase + (size_t)row * D_EMB + k0 + kq * 4);
                uint2 bu = *reinterpret_cast<const uint2*>(Bbase + (size_t)row * D_EMB + k0 + kq * 4);
                __nv_bfloat162 a0 = *reinterpret_cast<__nv_bfloat162*>(&au.x);
                __nv_bfloat162 a1 = *reinterpret_cast<__nv_bfloat162*>(&au.y);
                __nv_bfloat162 b0 = *reinterpret_cast<__nv_bfloat162*>(&bu.x);
                __nv_bfloat162 b1 = *reinterpret_cast<__nv_bfloat162*>(&bu.y);
                float2 af0 = __bfloat1622float2(a0), af1 = __bfloat1622float2(a1);
                float2 bf0 = __bfloat1622float2(b0), bf1 = __bfloat1622float2(b1);
                int kk = kq * 4;
                As[kk + 0][row] = af0.x; As[kk + 1][row] = af0.y;
                As[kk + 2][row] = af1.x; As[kk + 3][row] = af1.y;
                Bs[kk + 0][row] = bf0.x; Bs[kk + 1][row] = bf0.y;
                Bs[kk + 2][row] = bf1.x; Bs[kk + 3][row] = bf1.y;
            }
            __syncthreads();

            #pragma unroll
            for (int k = 0; k < BK; k++) {
                float ar[8], br[8];
                #pragma unroll
                for (int r = 0; r < 8; r++) ar[r] = As[k][ty * 8 + r];
                #pragma unroll
                for (int c = 0; c < 8; c++) br[c] = Bs[k][tx * 8 + c];
                #pragma unroll
                for (int r = 0; r < 8; r++)
                    #pragma unroll
                    for (int c = 0; c < 8; c++)
                        acc[r][c] = fmaf(ar[r], br[c], acc[r][c]);
            }
        }

        #pragma unroll
        for (int r = 0; r < 8; r++) {
            int mi = ty * 8 + r;
            int gi = iBase + mi;
            int li = lA[mi];
            #pragma unroll
            for (int c = 0; c < 8; c++) {
                int nj = tx * 8 + c;
                int gj = jb + nj;
                float s = acc[r][c];
                float loss;
                if (li == lB[half * TILE_M + nj]) { float d = 1.0f - s;              loss = d * d; }
                else                              { float d = fmaxf(s - 0.5f, 0.0f); loss = d * d; }
                lsum += (gj > gi) ? 2.0f * loss : 0.0f;
            }
        }
        __syncthreads();
    }

    #pragma unroll
    for (int o = 16; o > 0; o >>= 1) lsum += __shfl_xor_sync(0xffffffffu, lsum, o);
    if (lane == 0) red[w] = lsum;
    __syncthreads();
    if (t == 0) {
        float bs = 0.0f;
        #pragma unroll
        for (int i = 0; i < 8; i++) bs += red[i];
        atomicAdd(&g_acc, (double)bs);
        __threadfence();
        int old = atomicAdd(&g_done, 1);
        if (old == GRID_PAIR - 1) {
            __threadfence();
            double total = atomicAdd(&g_acc, 0.0);
            out[0] = (float)(total / ((double)N_EMB * (double)(N_EMB - 1)));
        }
    }
    #undef BK
#endif
}

extern "C" void kernel_launch(void* const* d_in, const int* in_sizes, int n_in,
                              void* d_out, int out_size) {
    const float* emb;
    const int*   lab;
    if (in_sizes[0] > in_sizes[1]) {
        emb = (const float*)d_in[0];
        lab = (const int*)d_in[1];
    } else {
        emb = (const float*)d_in[1];
        lab = (const int*)d_in[0];
    }
    float* out = (float*)d_out;

    // Idempotent; not a stream op, safe under graph capture.
    (void)cudaFuncSetAttribute(pair_loss_kernel,
                               cudaFuncAttributeMaxDynamicSharedMemorySize, SMEM_DYN);

    prep_normalize_kernel<<<N_EMB + 1, 128>>>(emb, lab);
    pair_loss_kernel<<<GRID_PAIR, 256, SMEM_DYN>>>(out);
}

// round 11
// speedup vs baseline: 11.4402x; 1.1418x over previous
#include <cuda_runtime.h>
#include <cuda_bf16.h>
#include <math.h>
#include <stdint.h>

#define N_EMB 8192
#define D_EMB 512
#define TILE_M 128
#define TILE_N 256
#define KCHUNK 64
#define NCHUNKS (D_EMB / KCHUNK)                  // 8
#define NT_M (N_EMB / TILE_M)                     // 64
#define NT_N (N_EMB / TILE_N)                     // 32
#define GRID_PAIR (NT_N * (NT_N + 1))             // 1056
#define TMEM_COLS 256
#define A_STAGE 16384
#define B_STAGE 32768
#define STAGE_BYTES (A_STAGE + B_STAGE)           // 49152
#define SMEM_DYN (2 * STAGE_BYTES + 1024)         // 99328
#define BLK_BYTES 16384                            // one [128 rows][128B] block

// Scratch (allocation-free): tiled, pre-swizzled bf16 normalized embeddings.
// Layout: block index = kc*NT_M + tile  (kc = k/64, tile = row/128),
// within block: sw128(r*128 + c*2) bytes, r = row&127, c = k&63.
__device__ __nv_bfloat16 g_tiles[NCHUNKS * NT_M * 8192];  // 8 MB
__device__ int    g_labels[N_EMB];
__device__ double g_acc;
__device__ int    g_done;

// ---------------------------------------------------------------------------
// PTX helpers
// ---------------------------------------------------------------------------
__device__ __forceinline__ uint32_t smem_u32(const void* p) {
    uint32_t a;
    asm("{ .reg .u64 t; cvta.to.shared.u64 t, %1; cvt.u32.u64 %0, t; }" : "=r"(a) : "l"(p));
    return a;
}
__device__ __forceinline__ uint32_t elect_one() {
    uint32_t r;
    asm volatile("{\n\t.reg .pred p;\n\telect.sync _|p, 0xFFFFFFFF;\n\tselp.b32 %0, 1, 0, p;\n\t}" : "=r"(r));
    return r;
}
#define MBARRIER_INIT(addr, cnt) \
    asm volatile("mbarrier.init.shared.b64 [%0], %1;" :: "r"(addr), "r"(cnt) : "memory")
#define MBARRIER_EXPECT_TX(addr, tx) \
    asm volatile("mbarrier.arrive.expect_tx.shared.b64 _, [%0], %1;" :: "r"(addr), "r"(tx) : "memory")
#define MBARRIER_WAIT_P0(addr) do { \
    uint32_t _m = (addr); uint32_t _done; \
    asm volatile("{\n\t.reg .pred p;\n\tmbarrier.try_wait.parity.acquire.cta.shared::cta.b64 p, [%1], 0;\n\tselp.b32 %0,1,0,p;\n\t}" \
        : "=r"(_done) : "r"(_m) : "memory"); \
    if (!_done) { \
        asm volatile("{\n\t.reg .pred P1;\n\tWL_%=:\n\tmbarrier.try_wait.parity.acquire.cta.shared::cta.b64 P1, [%0], 0, 0x989680;\n\t@P1 bra.uni WD_%=;\n\tbra.uni WL_%=;\n\tWD_%=:\n\t}" \
            :: "r"(_m) : "memory"); \
    } } while (0)
// Plain bulk copy gmem->smem, mbarrier complete_tx (no tensormap needed).
#define CP_BULK(dst, src, bytes, mbar) \
    asm volatile("cp.async.bulk.shared::cta.global.mbarrier::complete_tx::bytes [%0], [%1], %2, [%3];" \
        :: "r"(dst), "l"(src), "r"(bytes), "r"(mbar) : "memory")

__device__ __forceinline__ uint32_t sw128(uint32_t off) { return off ^ ((off >> 3) & 0x70); }

// bf16 element index into g_tiles for logical (row, k)
__device__ __forceinline__ int tiled_idx(int row, int k) {
    int tile = row >> 7, r = row & 127;
    int kc = k >> 6, c = k & 63;
    uint32_t off = sw128((uint32_t)(r * 128 + c * 2));
    return (kc * NT_M + tile) * 8192 + (int)(off >> 1);
}

#ifdef __CUDA_ARCH_FEAT_SM103_ALL
// ---- tcgen05 wrappers: ONLY compiled in the sm_103a feature pass ----------
#define TCGEN05_ALLOC(sa, n) \
    asm volatile("tcgen05.alloc.cta_group::1.sync.aligned.shared::cta.b32 [%0], %1;" :: "r"(sa), "r"(n) : "memory")
#define TCGEN05_DEALLOC(tm, n) \
    asm volatile("tcgen05.dealloc.cta_group::1.sync.aligned.b32 %0, %1;" :: "r"(tm), "r"(n))
#define TCGEN05_RELINQ() \
    asm volatile("tcgen05.relinquish_alloc_permit.cta_group::1.sync.aligned;")
#define TCGEN05_COMMIT(mb) \
    asm volatile("tcgen05.commit.cta_group::1.mbarrier::arrive::one.shared::cluster.b64 [%0];" :: "r"(mb) : "memory")
#define TCGEN05_FENCE_AFTER()  asm volatile("tcgen05.fence::after_thread_sync;" ::: "memory")
#define TCGEN05_FENCE_BEFORE() asm volatile("tcgen05.fence::before_thread_sync;" ::: "memory")
#define TCGEN05_WAIT_LD()      asm volatile("tcgen05.wait::ld.sync.aligned;" ::: "memory")
#define TCGEN05_LD_X32(r, ta) \
    asm volatile("tcgen05.ld.sync.aligned.32x32b.x32.b32 " \
        "{%0,%1,%2,%3,%4,%5,%6,%7,%8,%9,%10,%11,%12,%13,%14,%15," \
        "%16,%17,%18,%19,%20,%21,%22,%23,%24,%25,%26,%27,%28,%29,%30,%31}, [%32];" \
        : "=r"((r)[0]),"=r"((r)[1]),"=r"((r)[2]),"=r"((r)[3]),"=r"((r)[4]),"=r"((r)[5]),"=r"((r)[6]),"=r"((r)[7]), \
          "=r"((r)[8]),"=r"((r)[9]),"=r"((r)[10]),"=r"((r)[11]),"=r"((r)[12]),"=r"((r)[13]),"=r"((r)[14]),"=r"((r)[15]), \
          "=r"((r)[16]),"=r"((r)[17]),"=r"((r)[18]),"=r"((r)[19]),"=r"((r)[20]),"=r"((r)[21]),"=r"((r)[22]),"=r"((r)[23]), \
          "=r"((r)[24]),"=r"((r)[25]),"=r"((r)[26]),"=r"((r)[27]),"=r"((r)[28]),"=r"((r)[29]),"=r"((r)[30]),"=r"((r)[31]) \
        : "r"(ta))

// SS-mode bf16 MMA, cg1: D[M=128,N=256] += A[128,K16] * B[256,K16]^T
__device__ __forceinline__ void mma_f16_ss(uint32_t d_tmem, uint64_t a_desc, uint64_t b_desc,
                                           uint32_t idesc, uint32_t enable_d) {
    asm volatile(
        "{\n\t.reg .pred p;\n\tsetp.ne.u32 p, %4, 0;\n\t"
        "tcgen05.mma.cta_group::1.kind::f16 [%0], %1, %2, %3, {%5,%5,%5,%5}, p;\n\t}"
        :: "r"(d_tmem), "l"(a_desc), "l"(b_desc), "r"(idesc), "r"(enable_d), "r"(0u)
        : "memory");
}
#endif  // __CUDA_ARCH_FEAT_SM103_ALL

// SW128 K-major smem descriptor base (layout=SW128, version=1, SBO=64, LBO=1)
__device__ static const uint64_t DESC_BASE =
    (2ull << 61) | (1ull << 46) | (64ull << 32) | (1ull << 16);
// idesc: F32 accum (1<<4), bf16 A (1<<7), bf16 B (1<<10), N=256 (32<<17), M=128 (8<<24)
#define MMA_IDESC 0x8400490u

// ---------------------------------------------------------------------------
// Kernel 1: fused label-prep + L2 normalize, writing the tiled swizzled
// layout. Grid = N_EMB + 1; 128 threads. Thread tid owns floats k0=tid*4..+3,
// which land as one 8-byte store inside one K-chunk block.
// ---------------------------------------------------------------------------
__global__ void prep_normalize_kernel(const float* __restrict__ emb,
                                      const int* __restrict__ raw) {
    if (blockIdx.x == N_EMB) {
        __shared__ int s_or[128];
        int t = threadIdx.x;
        s_or[t] = raw[2 * t + 1];
        __syncthreads();
        for (int s = 64; s > 0; s >>= 1) {
            if (t < s) s_or[t] |= s_or[t + s];
            __syncthreads();
        }
        int is64 = (s_or[0] == 0);
        for (int i = t; i < N_EMB; i += 128) g_labels[i] = is64 ? raw[2 * i] : raw[i];
        if (t == 0) { g_acc = 0.0; g_done = 0; }
        return;
    }
    int row = blockIdx.x;
    const float4* src = reinterpret_cast<const float4*>(emb + (size_t)row * D_EMB);
    float4 v = src[threadIdx.x];
    float ss = v.x * v.x + v.y * v.y + v.z * v.z + v.w * v.w;
    #pragma unroll
    for (int o = 16; o > 0; o >>= 1) ss += __shfl_xor_sync(0xffffffffu, ss, o);
    __shared__ float ws[4];
    int lane = threadIdx.x & 31, w = threadIdx.x >> 5;
    if (lane == 0) ws[w] = ss;
    __syncthreads();
    float tot = ws[0] + ws[1] + ws[2] + ws[3];
    float inv = 1.0f / fmaxf(sqrtf(tot), 1e-12f);
    __nv_bfloat162 p0 = __float22bfloat162_rn(make_float2(v.x * inv, v.y * inv));
    __nv_bfloat162 p1 = __float22bfloat162_rn(make_float2(v.z * inv, v.w * inv));
    uint2 o2;
    o2.x = *reinterpret_cast<uint32_t*>(&p0);
    o2.y = *reinterpret_cast<uint32_t*>(&p1);
    int k0 = threadIdx.x * 4;
    int idx = tiled_idx(row, k0);   // 8B-aligned (k0 multiple of 4)
    *reinterpret_cast<uint2*>(&g_tiles[idx]) = o2;
}

// ---------------------------------------------------------------------------
// Kernel 2: pairwise Gram-tile + loss + fused finalize.
// Tiles: M=128 rows (ti) x N=256 cols (cj), ti <= 2cj+1 => 1056 tiles.
// Per-element weight gj>gi ? 2 : 0.
//   sm_103a: single-thread bulk-DMA + tcgen05 pipeline; TMEM epilogue.
//   other passes: SIMT fallback (compile-safety; not selected on GB300).
// ---------------------------------------------------------------------------
extern __shared__ char dynsmem[];

__global__ __launch_bounds__(256, 2)
void pair_loss_kernel(float* __restrict__ out) {
    // Decode linear block id -> (cj, ti). offset(cj) = cj*(cj+1).
    int b = blockIdx.x;
    int cj = (int)((sqrtf(4.0f * (float)b + 1.0f) - 1.0f) * 0.5f);
    if (cj < 0) cj = 0;
    if (cj > NT_N - 1) cj = NT_N - 1;
    while (cj * (cj + 1) > b) cj--;
    while ((cj + 1) * (cj + 2) <= b) cj++;
    int ti = b - cj * (cj + 1);
    int iBase = ti * TILE_M;
    int jBase = cj * TILE_N;

    int t = threadIdx.x, lane = t & 31, w = t >> 5;

#ifdef __CUDA_ARCH_FEAT_SM103_ALL
    // ============================ tcgen05 path =============================
    __shared__ uint32_t s_tmem;
    __shared__ alignas(8) unsigned long long s_mbarL[NCHUNKS];  // load done
    __shared__ alignas(8) unsigned long long s_mbarM[NCHUNKS];  // mma done
    __shared__ int sLA[TILE_M], sLB[TILE_N];
    __shared__ float s_red[8];

    uint32_t base = (smem_u32(dynsmem) + 1023u) & ~1023u;
    uint32_t mbarL = smem_u32(s_mbarL);
    uint32_t mbarM = smem_u32(s_mbarM);

    if (t < TILE_M) sLA[t] = g_labels[iBase + t];
    sLB[t] = g_labels[jBase + t];
    if (t == 0) {
        #pragma unroll
        for (int i = 0; i < NCHUNKS; i++) {
            MBARRIER_INIT(mbarL + 8 * i, 1);
            MBARRIER_INIT(mbarM + 8 * i, 1);
        }
    }
    if (w == 0) TCGEN05_ALLOC(smem_u32(&s_tmem), TMEM_COLS);
    __syncthreads();
    uint32_t tmem;
    asm volatile("ld.shared.b32 %0, [%1];" : "=r"(tmem) : "r"(smem_u32(&s_tmem)));

    // -------- single-thread bulk-DMA + MMA state machine --------
    if (w == 0) {
        if (elect_one()) {
            const char* tb = (const char*)g_tiles;
            // prologue: chunk 0 loads
            {
                uint32_t buf = base;
                MBARRIER_EXPECT_TX(mbarL, (uint32_t)STAGE_BYTES);
                CP_BULK(buf,           tb + ((size_t)(0 * NT_M + ti) * BLK_BYTES),     (uint32_t)A_STAGE, mbarL);
                CP_BULK(buf + A_STAGE, tb + ((size_t)(0 * NT_M + 2 * cj) * BLK_BYTES), (uint32_t)B_STAGE, mbarL);
            }
            for (int kc = 0; kc < NCHUNKS; kc++) {
                if (kc + 1 < NCHUNKS) {
                    if (kc >= 1) MBARRIER_WAIT_P0(mbarM + 8 * (kc - 1));  // frees buf (kc+1)&1
                    uint32_t buf = base + (uint32_t)((kc + 1) & 1) * STAGE_BYTES;
                    uint32_t lm = mbarL + 8 * (kc + 1);
                    MBARRIER_EXPECT_TX(lm, (uint32_t)STAGE_BYTES);
                    CP_BULK(buf,           tb + ((size_t)((kc + 1) * NT_M + ti) * BLK_BYTES),     (uint32_t)A_STAGE, lm);
                    CP_BULK(buf + A_STAGE, tb + ((size_t)((kc + 1) * NT_M + 2 * cj) * BLK_BYTES), (uint32_t)B_STAGE, lm);
                }
                MBARRIER_WAIT_P0(mbarL + 8 * kc);
                uint32_t buf = base + (uint32_t)(kc & 1) * STAGE_BYTES;
                uint64_t ad = DESC_BASE | ((uint64_t)(buf >> 4) & 0x3FFFull);
                uint64_t bd = DESC_BASE | ((uint64_t)((buf + A_STAGE) >> 4) & 0x3FFFull);
                #pragma unroll
                for (int s = 0; s < 4; s++) {
                    mma_f16_ss(tmem, ad + (uint64_t)(s * 2), bd + (uint64_t)(s * 2),
                               MMA_IDESC, (kc > 0 || s > 0) ? 1u : 0u);
                }
                TCGEN05_COMMIT(mbarM + 8 * kc);
            }
        }
    }

    // All threads wait for the final MMA (in-order pipe => all done).
    MBARRIER_WAIT_P0(mbarM + 8 * (NCHUNKS - 1));
    TCGEN05_FENCE_AFTER();

    // Epilogue: warp w (SMSP w&3) covers TMEM rows (w&3)*32+lane,
    // columns (w>>2)*128 .. +127 in four x32 loads.
    int sp = w & 3;
    int m = sp * 32 + lane;
    int gi = iBase + m;
    int li = sLA[m];
    uint32_t woff = (uint32_t)sp << 21;

    float lsum = 0.0f;
    #pragma unroll
    for (int cb = 0; cb < 4; cb++) {
        int c0 = (w >> 2) * 128 + cb * 32;
        uint32_t regs[32];
        TCGEN05_LD_X32(regs, tmem + (uint32_t)c0 + woff);
        TCGEN05_WAIT_LD();
        #pragma unroll
        for (int c = 0; c < 32; c++) {
            int n = c0 + c;
            int gj = jBase + n;
            float s = __uint_as_float(regs[c]);
            float loss;
            if (li == sLB[n]) { float d = 1.0f - s;              loss = d * d; }
            else              { float d = fmaxf(s - 0.5f, 0.0f); loss = d * d; }
            lsum += (gj > gi) ? 2.0f * loss : 0.0f;
        }
    }
    TCGEN05_FENCE_BEFORE();

    #pragma unroll
    for (int o = 16; o > 0; o >>= 1) lsum += __shfl_xor_sync(0xffffffffu, lsum, o);
    if (lane == 0) s_red[w] = lsum;
    __syncthreads();
    if (t == 0) {
        float bs = 0.0f;
        #pragma unroll
        for (int i = 0; i < 8; i++) bs += s_red[i];
        atomicAdd(&g_acc, (double)bs);
        __threadfence();
        int old = atomicAdd(&g_done, 1);
        if (old == GRID_PAIR - 1) {
            __threadfence();
            double total = atomicAdd(&g_acc, 0.0);
            out[0] = (float)(total / ((double)N_EMB * (double)(N_EMB - 1)));
        }
    }

    __syncthreads();
    if (w == 0) {
        TCGEN05_RELINQ();
        TCGEN05_DEALLOC(tmem, TMEM_COLS);
    }
#else
    // ===================== SIMT fallback (compile-only) ====================
    #define BK 16
    __shared__ float As[BK][TILE_M];
    __shared__ float Bs[BK][TILE_M];
    __shared__ int   lA[TILE_M];
    __shared__ int   lB[TILE_N];
    __shared__ float red[8];

    int tx = t & 15;
    int ty = t >> 4;

    if (t < TILE_M) lA[t] = g_labels[iBase + t];
    lB[t] = g_labels[jBase + t];

    float lsum = 0.0f;
    for (int half = 0; half < 2; half++) {
        int jb = jBase + half * TILE_M;

        float acc[8][8];
        #pragma unroll
        for (int r = 0; r < 8; r++)
            #pragma unroll
            for (int c = 0; c < 8; c++) acc[r][c] = 0.0f;

        for (int k0 = 0; k0 < D_EMB; k0 += BK) {
            __syncthreads();
            #pragma unroll
            for (int rep = 0; rep < 2; rep++) {
                int f   = t + rep * 256;
                int row = f >> 2;
                int kq  = f & 3;
                int ka  = k0 + kq * 4;
                uint2 au = *reinterpret_cast<const uint2*>(&g_tiles[tiled_idx(iBase + row, ka)]);
                uint2 bu = *reinterpret_cast<const uint2*>(&g_tiles[tiled_idx(jb + row, ka)]);
                __nv_bfloat162 a0 = *reinterpret_cast<__nv_bfloat162*>(&au.x);
                __nv_bfloat162 a1 = *reinterpret_cast<__nv_bfloat162*>(&au.y);
                __nv_bfloat162 b0 = *reinterpret_cast<__nv_bfloat162*>(&bu.x);
                __nv_bfloat162 b1 = *reinterpret_cast<__nv_bfloat162*>(&bu.y);
                float2 af0 = __bfloat1622float2(a0), af1 = __bfloat1622float2(a1);
                float2 bf0 = __bfloat1622float2(b0), bf1 = __bfloat1622float2(b1);
                int kk = kq * 4;
                As[kk + 0][row] = af0.x; As[kk + 1][row] = af0.y;
                As[kk + 2][row] = af1.x; As[kk + 3][row] = af1.y;
                Bs[kk + 0][row] = bf0.x; Bs[kk + 1][row] = bf0.y;
                Bs[kk + 2][row] = bf1.x; Bs[kk + 3][row] = bf1.y;
            }
            __syncthreads();

            #pragma unroll
            for (int k = 0; k < BK; k++) {
                float ar[8], br[8];
                #pragma unroll
                for (int r = 0; r < 8; r++) ar[r] = As[k][ty * 8 + r];
                #pragma unroll
                for (int c = 0; c < 8; c++) br[c] = Bs[k][tx * 8 + c];
                #pragma unroll
                for (int r = 0; r < 8; r++)
                    #pragma unroll
                    for (int c = 0; c < 8; c++)
                        acc[r][c] = fmaf(ar[r], br[c], acc[r][c]);
            }
        }

        #pragma unroll
        for (int r = 0; r < 8; r++) {
            int mi = ty * 8 + r;
            int gi = iBase + mi;
            int li = lA[mi];
            #pragma unroll
            for (int c = 0; c < 8; c++) {
                int nj = tx * 8 + c;
                int gj = jb + nj;
                float s = acc[r][c];
                float loss;
                if (li == lB[half * TILE_M + nj]) { float d = 1.0f - s;              loss = d * d; }
                else                              { float d = fmaxf(s - 0.5f, 0.0f); loss = d * d; }
                lsum += (gj > gi) ? 2.0f * loss : 0.0f;
            }
        }
        __syncthreads();
    }

    #pragma unroll
    for (int o = 16; o > 0; o >>= 1) lsum += __shfl_xor_sync(0xffffffffu, lsum, o);
    if (lane == 0) red[w] = lsum;
    __syncthreads();
    if (t == 0) {
        float bs = 0.0f;
        #pragma unroll
        for (int i = 0; i < 8; i++) bs += red[i];
        atomicAdd(&g_acc, (double)bs);
        __threadfence();
        int old = atomicAdd(&g_done, 1);
        if (old == GRID_PAIR - 1) {
            __threadfence();
            double total = atomicAdd(&g_acc, 0.0);
            out[0] = (float)(total / ((double)N_EMB * (double)(N_EMB - 1)));
        }
    }
    #undef BK
#endif
}

extern "C" void kernel_launch(void* const* d_in, const int* in_sizes, int n_in,
                              void* d_out, int out_size) {
    const float* emb;
    const int*   lab;
    if (in_sizes[0] > in_sizes[1]) {
        emb = (const float*)d_in[0];
        lab = (const int*)d_in[1];
    } else {
        emb = (const float*)d_in[1];
        lab = (const int*)d_in[0];
    }
    float* out = (float*)d_out;

    // Idempotent; not a stream op, safe under graph capture.
    (void)cudaFuncSetAttribute(pair_loss_kernel,
                               cudaFuncAttributeMaxDynamicSharedMemorySize, SMEM_DYN);

    prep_normalize_kernel<<<N_EMB + 1, 128>>>(emb, lab);
    pair_loss_kernel<<<GRID_PAIR, 256, SMEM_DYN>>>(out);
}